// round 14
// baseline (speedup 1.0000x reference)
#include <cuda_runtime.h>
#include <cuda_fp16.h>
#include <math.h>

#define NN 50000
#define NE 1600000
#define HH 4
#define FF 128
#define NBLK 49                 // ceil(50000/1024)
#define NODE_BLOCKS 6250        // NN*32/256
#define HIST_BLOCKS 3125        // (NE/2)/256 int4-loads
#define LOG2E 1.4426950408889634f

typedef unsigned long long u64;

// ---------------- scratch ----------------------------------------------------
__device__ int    g_is64;
__device__ int    g_deg[NN];          // zero at load; re-zeroed by k_scatter each call
__device__ int    g_off[NN + 1];
__device__ int    g_cursor[NN];
__device__ float4 g_ssrc[NN];         // pre-scaled by log2(e)
__device__ float4 g_sdst[NN];         // pre-scaled by log2(e)
__device__ int    g_dst[NE + 16];     // dst stream (padded for deep prefetch)
__device__ uint2  g_wh[NE];           // 4x half weights per edge
__device__ __half g_xh[(size_t)NN * FF];   // fp16 copy of x

// ---------------- f32x2 helpers ----------------------------------------------
__device__ __forceinline__ u64 pack2(float a, float b) {
    u64 r; asm("mov.b64 %0,{%1,%2};" : "=l"(r) : "f"(a), "f"(b)); return r;
}
__device__ __forceinline__ u64 dup2(float a) { return pack2(a, a); }
__device__ __forceinline__ void unpk2(u64 v, float& a, float& b) {
    asm("mov.b64 {%0,%1},%2;" : "=f"(a), "=f"(b) : "l"(v));
}
__device__ __forceinline__ u64 ffma2(u64 a, u64 b, u64 c) {
    u64 d; asm("fma.rn.f32x2 %0,%1,%2,%3;" : "=l"(d) : "l"(a), "l"(b), "l"(c)); return d;
}
__device__ __forceinline__ u64 fadd2(u64 a, u64 b) {
    u64 d; asm("add.rn.f32x2 %0,%1,%2;" : "=l"(d) : "l"(a), "l"(b)); return d;
}

// ---------------- 1) fused prep (scores + xh + detect) & hist ----------------
__global__ void __launch_bounds__(256) k_prep(const float* __restrict__ x,
                                              const float* __restrict__ wp,
                                              const float* __restrict__ ap,
                                              const int* __restrict__ ei) {
    int b = blockIdx.x;
    if (b >= NODE_BLOCKS) {
        // histogram: coalesced int4 over the src array
        int t = (b - NODE_BLOCKS) * 256 + threadIdx.x;   // int4 index < NE/2
        int4 v = ((const int4*)ei)[t];
        __shared__ int any32;
        if (threadIdx.x == 0) any32 = 0;
        __syncthreads();
        if ((v.y | v.w) != 0) any32 = 1;
        __syncthreads();
        if (any32 == 0) {                 // int64 layout
            atomicAdd(&g_deg[v.x], 1);
            atomicAdd(&g_deg[v.z], 1);
        } else if (t < NE / 4) {          // int32 layout
            atomicAdd(&g_deg[v.x], 1);
            atomicAdd(&g_deg[v.y], 1);
            atomicAdd(&g_deg[v.z], 1);
            atomicAdd(&g_deg[v.w], 1);
        }
        return;
    }

    int tid = b * 256 + threadIdx.x;
    if (tid == 0) g_off[NN] = NE;
    if (b == 0) {
        __shared__ int bad;
        if (threadIdx.x == 0) bad = 0;
        __syncthreads();
        for (int k = threadIdx.x; k < 4096; k += 256)
            if (ei[2 * k + 1] != 0) bad = 1;
        __syncthreads();
        if (threadIdx.x == 0) g_is64 = (bad == 0) ? 1 : 0;
    }

    int gw   = tid >> 5;
    int lane = threadIdx.x & 31;
    int f = lane * 4;
    float4 xv = *(const float4*)(x + (size_t)gw * FF + f);

    // fp16 copy of x row for the agg gather
    *(__half2*)(g_xh + (size_t)gw * FF + f)     = __floats2half2_rn(xv.x, xv.y);
    *(__half2*)(g_xh + (size_t)gw * FF + f + 2) = __floats2half2_rn(xv.z, xv.w);

    float ss[HH], sd[HH];
    #pragma unroll
    for (int h = 0; h < HH; h++) {
        float4 wv = *(const float4*)(wp + h * FF + f);
        float4 as = *(const float4*)(ap + h * 2 * FF + f);
        float4 ad = *(const float4*)(ap + h * 2 * FF + FF + f);
        float4 hw = make_float4(xv.x * wv.x, xv.y * wv.y, xv.z * wv.z, xv.w * wv.w);
        float hs = hw.x * as.x + hw.y * as.y + hw.z * as.z + hw.w * as.w;
        float hd = hw.x * ad.x + hw.y * ad.y + hw.z * ad.z + hw.w * ad.w;
        #pragma unroll
        for (int o = 16; o; o >>= 1) {
            hs += __shfl_xor_sync(0xffffffffu, hs, o);
            hd += __shfl_xor_sync(0xffffffffu, hd, o);
        }
        ss[h] = hs * LOG2E; sd[h] = hd * LOG2E;   // pre-scale for ex2
    }
    if (lane == 0) {
        g_ssrc[gw] = make_float4(ss[0], ss[1], ss[2], ss[3]);
        g_sdst[gw] = make_float4(sd[0], sd[1], sd[2], sd[3]);
    }
}

// ---------------- 2) one-shot scan -------------------------------------------
__global__ void k_scan() {
    __shared__ int wsum[32];
    __shared__ int redsum[32];
    int b = blockIdx.x, t = threadIdx.x, lane = t & 31, wid = t >> 5;

    int pre = b * 1024;
    int acc = 0;
    for (int i = t; i < pre; i += 1024) acc += g_deg[i];
    #pragma unroll
    for (int o = 16; o; o >>= 1) acc += __shfl_xor_sync(0xffffffffu, acc, o);
    if (lane == 0) redsum[wid] = acc;
    __syncthreads();
    int bofs;
    {
        int v = redsum[lane];
        #pragma unroll
        for (int o = 16; o; o >>= 1) v += __shfl_xor_sync(0xffffffffu, v, o);
        bofs = __shfl_sync(0xffffffffu, v, 0);
    }

    int i = pre + t;
    int v = (i < NN) ? g_deg[i] : 0;
    int inc = v;
    #pragma unroll
    for (int o = 1; o < 32; o <<= 1) {
        int u = __shfl_up_sync(0xffffffffu, inc, o);
        if (lane >= o) inc += u;
    }
    if (lane == 31) wsum[wid] = inc;
    __syncthreads();
    if (wid == 0) {
        int s = wsum[lane];
        #pragma unroll
        for (int o = 1; o < 32; o <<= 1) {
            int u = __shfl_up_sync(0xffffffffu, s, o);
            if (lane >= o) s += u;
        }
        wsum[lane] = s;
    }
    __syncthreads();
    int excl = bofs + (wid ? wsum[wid - 1] : 0) + inc - v;
    if (i < NN) { g_off[i] = excl; g_cursor[i] = excl; }
}

// ---------------- 3) scatter: split dst / weight streams ---------------------
__device__ __forceinline__ float edge_w(float s2) {
    // scores pre-scaled by log2e: w = 2^min(-s2, -0.2*s2)
    float e = fminf(-s2, -0.2f * s2);
    float r; asm("ex2.approx.f32 %0,%1;" : "=f"(r) : "f"(e));
    return r;
}
__global__ void __launch_bounds__(256) k_scatter(const int* __restrict__ ei) {
    int i = blockIdx.x * blockDim.x + threadIdx.x;
    if (i < NN) g_deg[i] = 0;              // restore invariant for next call
    if (i >= NE / 2) return;               // 2 edges per thread
    int s0, s1, d0, d1;
    if (g_is64) {
        int4 sv = ((const int4*)ei)[i];
        int4 dv = ((const int4*)ei)[NE / 2 + i];
        s0 = sv.x; s1 = sv.z; d0 = dv.x; d1 = dv.z;
    } else {
        int2 sv = ((const int2*)ei)[i];
        int2 dv = ((const int2*)ei)[NE / 2 + i];
        s0 = sv.x; s1 = sv.y; d0 = dv.x; d1 = dv.y;
    }
    float4 a0 = g_ssrc[s0], b0 = g_sdst[d0];
    float4 a1 = g_ssrc[s1], b1 = g_sdst[d1];

    __half2 w001 = __floats2half2_rn(edge_w(a0.x + b0.x), edge_w(a0.y + b0.y));
    __half2 w023 = __floats2half2_rn(edge_w(a0.z + b0.z), edge_w(a0.w + b0.w));
    __half2 w101 = __floats2half2_rn(edge_w(a1.x + b1.x), edge_w(a1.y + b1.y));
    __half2 w123 = __floats2half2_rn(edge_w(a1.z + b1.z), edge_w(a1.w + b1.w));

    int p0 = atomicAdd(&g_cursor[s0], 1);
    int p1 = atomicAdd(&g_cursor[s1], 1);

    g_wh[p0] = make_uint2(*reinterpret_cast<unsigned*>(&w001),
                          *reinterpret_cast<unsigned*>(&w023));
    g_dst[p0] = d0;
    g_wh[p1] = make_uint2(*reinterpret_cast<unsigned*>(&w101),
                          *reinterpret_cast<unsigned*>(&w123));
    g_dst[p1] = d1;
}

// ---------------- 4) aggregation: depth-2 x prefetch, inline L1-hot weights --
__global__ void __launch_bounds__(256, 4) k_agg(const float* __restrict__ wp,
                                                float* __restrict__ out) {
    int gw   = (blockIdx.x * blockDim.x + threadIdx.x) >> 5;
    int lane = threadIdx.x & 31;
    if (gw >= NN) return;
    int beg = g_off[gw];
    int n   = g_off[gw + 1] - beg;
    int f = lane * 4;
    const int*   dp  = g_dst + beg;
    const uint2* whp = g_wh + beg;

    u64 acc[HH][2];
    #pragma unroll
    for (int h = 0; h < HH; h++) { acc[h][0] = 0ull; acc[h][1] = 0ull; }
    u64 rs01 = 0ull, rs23 = 0ull;

    // prologue: chunk0 dsts -> gather xA, then chunk1 dsts
    int dstB[4];
    int2 xA[4];
    #pragma unroll
    for (int k = 0; k < 4; k++) dstB[k] = __ldg(dp + k);            // padded: safe
    #pragma unroll
    for (int k = 0; k < 4; k++)
        xA[k] = __ldg((const int2*)(g_xh + (size_t)dstB[k] * FF + f));
    #pragma unroll
    for (int k = 0; k < 4; k++) dstB[k] = __ldg(dp + 4 + k);        // chunk 1

    for (int c = 0; c < n; c += 4) {
        // prefetch: gather x for chunk c+1 (dsts loaded last iteration)
        int2 xB[4];
        #pragma unroll
        for (int k = 0; k < 4; k++)
            xB[k] = __ldg((const int2*)(g_xh + (size_t)dstB[k] * FF + f));
        // prefetch dsts for chunk c+2 (beg+c+8+k <= NE+11 < NE+16: safe)
        #pragma unroll
        for (int k = 0; k < 4; k++) dstB[k] = __ldg(dp + c + 8 + k);
        // math on chunk c; weights inline (broadcast, L1-hot), predicated for tail
        #pragma unroll
        for (int k = 0; k < 4; k++) {
            uint2 wh = (c + k < n) ? __ldg(whp + c + k) : make_uint2(0u, 0u);
            __half2 hw01 = *reinterpret_cast<__half2*>(&wh.x);
            __half2 hw23 = *reinterpret_cast<__half2*>(&wh.y);
            float2 w01 = __half22float2(hw01);
            float2 w23 = __half22float2(hw23);
            rs01 = fadd2(rs01, pack2(w01.x, w01.y));
            rs23 = fadd2(rs23, pack2(w23.x, w23.y));
            __half2 hx01 = *reinterpret_cast<__half2*>(&xA[k].x);
            __half2 hx23 = *reinterpret_cast<__half2*>(&xA[k].y);
            float2 x01 = __half22float2(hx01);
            float2 x23 = __half22float2(hx23);
            u64 xv01 = pack2(x01.x, x01.y);
            u64 xv23 = pack2(x23.x, x23.y);
            u64 p0 = dup2(w01.x), p1 = dup2(w01.y), p2 = dup2(w23.x), p3 = dup2(w23.y);
            acc[0][0] = ffma2(p0, xv01, acc[0][0]); acc[0][1] = ffma2(p0, xv23, acc[0][1]);
            acc[1][0] = ffma2(p1, xv01, acc[1][0]); acc[1][1] = ffma2(p1, xv23, acc[1][1]);
            acc[2][0] = ffma2(p2, xv01, acc[2][0]); acc[2][1] = ffma2(p2, xv23, acc[2][1]);
            acc[3][0] = ffma2(p3, xv01, acc[3][0]); acc[3][1] = ffma2(p3, xv23, acc[3][1]);
        }
        #pragma unroll
        for (int k = 0; k < 4; k++) xA[k] = xB[k];
    }

    float rs0, rs1, rs2, rs3;
    unpk2(rs01, rs0, rs1); unpk2(rs23, rs2, rs3);
    float inv[HH] = {1.0f / rs0, 1.0f / rs1, 1.0f / rs2, 1.0f / rs3};

    size_t base = (size_t)gw * FF + f;
    #pragma unroll
    for (int h = 0; h < HH; h++) {
        float4 wv = *(const float4*)(wp + h * FF + f);
        float a0, a1, a2, a3;
        unpk2(acc[h][0], a0, a1); unpk2(acc[h][1], a2, a3);
        __stcs((float4*)(out + (size_t)h * NN * FF + base),
            make_float4(a0 * wv.x * inv[h], a1 * wv.y * inv[h],
                        a2 * wv.z * inv[h], a3 * wv.w * inv[h]));
    }
}

// ---------------- launch -----------------------------------------------------
extern "C" void kernel_launch(void* const* d_in, const int* in_sizes, int n_in,
                              void* d_out, int out_size) {
    const float* x  = (const float*)d_in[0];
    const float* wp = (const float*)d_in[1];
    const float* ap = (const float*)d_in[2];
    const int*   ei = (const int*)d_in[3];
    float* out = (float*)d_out;

    const int TB = 256;
    k_prep<<<NODE_BLOCKS + HIST_BLOCKS, TB>>>(x, wp, ap, ei);
    k_scan<<<NBLK, 1024>>>();
    k_scatter<<<(NE / 2 + TB - 1) / TB, TB>>>(ei);
    k_agg<<<NODE_BLOCKS, TB>>>(wp, out);
}

// round 16
// speedup vs baseline: 1.0149x; 1.0149x over previous
#include <cuda_runtime.h>
#include <cuda_fp16.h>
#include <math.h>

#define NN 50000
#define NE 1600000
#define HH 4
#define FF 128
#define NBLK 49                 // ceil(50000/1024)
#define NODE_BLOCKS 6250        // NN*32/256
#define HIST_BLOCKS 3125        // (NE/2)/256 int4-loads
#define LOG2E 1.4426950408889634f

typedef unsigned long long u64;

// ---------------- scratch ----------------------------------------------------
__device__ int    g_is64;
__device__ int    g_deg[NN];          // zero at load; re-zeroed by k_scatter each call
__device__ int    g_off[NN + 1];
__device__ int    g_cursor[NN];
__device__ float4 g_ssrc[NN];         // pre-scaled by log2(e)
__device__ float4 g_sdst[NN];         // pre-scaled by log2(e)
__device__ int4   g_edges[NE + 16];   // {half2 w01, half2 w23, dst, 0}; padded (pad stays 0)
__device__ __half g_xh[(size_t)NN * FF];   // fp16 copy of x

// ---------------- f32x2 helpers ----------------------------------------------
__device__ __forceinline__ u64 pack2(float a, float b) {
    u64 r; asm("mov.b64 %0,{%1,%2};" : "=l"(r) : "f"(a), "f"(b)); return r;
}
__device__ __forceinline__ u64 dup2(float a) { return pack2(a, a); }
__device__ __forceinline__ void unpk2(u64 v, float& a, float& b) {
    asm("mov.b64 {%0,%1},%2;" : "=f"(a), "=f"(b) : "l"(v));
}
__device__ __forceinline__ u64 ffma2(u64 a, u64 b, u64 c) {
    u64 d; asm("fma.rn.f32x2 %0,%1,%2,%3;" : "=l"(d) : "l"(a), "l"(b), "l"(c)); return d;
}
__device__ __forceinline__ u64 fadd2(u64 a, u64 b) {
    u64 d; asm("add.rn.f32x2 %0,%1,%2;" : "=l"(d) : "l"(a), "l"(b)); return d;
}

// ---------------- 1) fused prep (scores + xh + detect) & hist ----------------
__global__ void __launch_bounds__(256) k_prep(const float* __restrict__ x,
                                              const float* __restrict__ wp,
                                              const float* __restrict__ ap,
                                              const int* __restrict__ ei) {
    int b = blockIdx.x;
    if (b >= NODE_BLOCKS) {
        // histogram: coalesced int4 over the src array
        int t = (b - NODE_BLOCKS) * 256 + threadIdx.x;   // int4 index < NE/2
        int4 v = ((const int4*)ei)[t];
        __shared__ int any32;
        if (threadIdx.x == 0) any32 = 0;
        __syncthreads();
        if ((v.y | v.w) != 0) any32 = 1;
        __syncthreads();
        if (any32 == 0) {                 // int64 layout
            atomicAdd(&g_deg[v.x], 1);
            atomicAdd(&g_deg[v.z], 1);
        } else if (t < NE / 4) {          // int32 layout
            atomicAdd(&g_deg[v.x], 1);
            atomicAdd(&g_deg[v.y], 1);
            atomicAdd(&g_deg[v.z], 1);
            atomicAdd(&g_deg[v.w], 1);
        }
        return;
    }

    int tid = b * 256 + threadIdx.x;
    if (tid == 0) g_off[NN] = NE;
    if (b == 0) {
        __shared__ int bad;
        if (threadIdx.x == 0) bad = 0;
        __syncthreads();
        for (int k = threadIdx.x; k < 4096; k += 256)
            if (ei[2 * k + 1] != 0) bad = 1;
        __syncthreads();
        if (threadIdx.x == 0) g_is64 = (bad == 0) ? 1 : 0;
    }

    int gw   = tid >> 5;
    int lane = threadIdx.x & 31;
    int f = lane * 4;
    float4 xv = *(const float4*)(x + (size_t)gw * FF + f);

    // fp16 copy of x row for the agg gather
    *(__half2*)(g_xh + (size_t)gw * FF + f)     = __floats2half2_rn(xv.x, xv.y);
    *(__half2*)(g_xh + (size_t)gw * FF + f + 2) = __floats2half2_rn(xv.z, xv.w);

    float ss[HH], sd[HH];
    #pragma unroll
    for (int h = 0; h < HH; h++) {
        float4 wv = *(const float4*)(wp + h * FF + f);
        float4 as = *(const float4*)(ap + h * 2 * FF + f);
        float4 ad = *(const float4*)(ap + h * 2 * FF + FF + f);
        float4 hw = make_float4(xv.x * wv.x, xv.y * wv.y, xv.z * wv.z, xv.w * wv.w);
        float hs = hw.x * as.x + hw.y * as.y + hw.z * as.z + hw.w * as.w;
        float hd = hw.x * ad.x + hw.y * ad.y + hw.z * ad.z + hw.w * ad.w;
        #pragma unroll
        for (int o = 16; o; o >>= 1) {
            hs += __shfl_xor_sync(0xffffffffu, hs, o);
            hd += __shfl_xor_sync(0xffffffffu, hd, o);
        }
        ss[h] = hs * LOG2E; sd[h] = hd * LOG2E;   // pre-scale for ex2
    }
    if (lane == 0) {
        g_ssrc[gw] = make_float4(ss[0], ss[1], ss[2], ss[3]);
        g_sdst[gw] = make_float4(sd[0], sd[1], sd[2], sd[3]);
    }
}

// ---------------- 2) one-shot scan -------------------------------------------
__global__ void k_scan() {
    __shared__ int wsum[32];
    __shared__ int redsum[32];
    int b = blockIdx.x, t = threadIdx.x, lane = t & 31, wid = t >> 5;

    int pre = b * 1024;
    int acc = 0;
    for (int i = t; i < pre; i += 1024) acc += g_deg[i];
    #pragma unroll
    for (int o = 16; o; o >>= 1) acc += __shfl_xor_sync(0xffffffffu, acc, o);
    if (lane == 0) redsum[wid] = acc;
    __syncthreads();
    int bofs;
    {
        int v = redsum[lane];
        #pragma unroll
        for (int o = 16; o; o >>= 1) v += __shfl_xor_sync(0xffffffffu, v, o);
        bofs = __shfl_sync(0xffffffffu, v, 0);
    }

    int i = pre + t;
    int v = (i < NN) ? g_deg[i] : 0;
    int inc = v;
    #pragma unroll
    for (int o = 1; o < 32; o <<= 1) {
        int u = __shfl_up_sync(0xffffffffu, inc, o);
        if (lane >= o) inc += u;
    }
    if (lane == 31) wsum[wid] = inc;
    __syncthreads();
    if (wid == 0) {
        int s = wsum[lane];
        #pragma unroll
        for (int o = 1; o < 32; o <<= 1) {
            int u = __shfl_up_sync(0xffffffffu, s, o);
            if (lane >= o) s += u;
        }
        wsum[lane] = s;
    }
    __syncthreads();
    int excl = bofs + (wid ? wsum[wid - 1] : 0) + inc - v;
    if (i < NN) { g_off[i] = excl; g_cursor[i] = excl; }
}

// ---------------- 3) scatter: single 16B record store ------------------------
__device__ __forceinline__ float edge_w(float s2) {
    // scores pre-scaled by log2e: w = 2^min(-s2, -0.2*s2)
    float e = fminf(-s2, -0.2f * s2);
    float r; asm("ex2.approx.f32 %0,%1;" : "=f"(r) : "f"(e));
    return r;
}
__global__ void __launch_bounds__(256) k_scatter(const int* __restrict__ ei) {
    int i = blockIdx.x * blockDim.x + threadIdx.x;
    if (i < NN) g_deg[i] = 0;              // restore invariant for next call
    if (i >= NE / 2) return;               // 2 edges per thread
    int s0, s1, d0, d1;
    if (g_is64) {
        int4 sv = ((const int4*)ei)[i];
        int4 dv = ((const int4*)ei)[NE / 2 + i];
        s0 = sv.x; s1 = sv.z; d0 = dv.x; d1 = dv.z;
    } else {
        int2 sv = ((const int2*)ei)[i];
        int2 dv = ((const int2*)ei)[NE / 2 + i];
        s0 = sv.x; s1 = sv.y; d0 = dv.x; d1 = dv.y;
    }
    float4 a0 = g_ssrc[s0], b0 = g_sdst[d0];
    float4 a1 = g_ssrc[s1], b1 = g_sdst[d1];

    __half2 w001 = __floats2half2_rn(edge_w(a0.x + b0.x), edge_w(a0.y + b0.y));
    __half2 w023 = __floats2half2_rn(edge_w(a0.z + b0.z), edge_w(a0.w + b0.w));
    __half2 w101 = __floats2half2_rn(edge_w(a1.x + b1.x), edge_w(a1.y + b1.y));
    __half2 w123 = __floats2half2_rn(edge_w(a1.z + b1.z), edge_w(a1.w + b1.w));

    int p0 = atomicAdd(&g_cursor[s0], 1);
    int p1 = atomicAdd(&g_cursor[s1], 1);

    int4 r0, r1;
    r0.x = *reinterpret_cast<int*>(&w001); r0.y = *reinterpret_cast<int*>(&w023);
    r0.z = d0; r0.w = 0;
    r1.x = *reinterpret_cast<int*>(&w101); r1.y = *reinterpret_cast<int*>(&w123);
    r1.z = d1; r1.w = 0;
    g_edges[p0] = r0;
    g_edges[p1] = r1;
}

// ---------------- 4) aggregation: dst-field deep prefetch, inline weights ----
__global__ void __launch_bounds__(256, 4) k_agg(const float* __restrict__ wp,
                                                float* __restrict__ out) {
    int gw   = (blockIdx.x * blockDim.x + threadIdx.x) >> 5;
    int lane = threadIdx.x & 31;
    if (gw >= NN) return;
    int beg = g_off[gw];
    int n   = g_off[gw + 1] - beg;
    int f = lane * 4;
    const int4* ep = g_edges + beg;

    u64 acc[HH][2];
    #pragma unroll
    for (int h = 0; h < HH; h++) { acc[h][0] = 0ull; acc[h][1] = 0ull; }
    u64 rs01 = 0ull, rs23 = 0ull;

    // prologue: dst fields of chunk0 -> gather xA; then dsts of chunk1
    int dstB[4];
    int2 xA[4];
    #pragma unroll
    for (int k = 0; k < 4; k++) dstB[k] = __ldg(&ep[k].z);         // padded: safe
    #pragma unroll
    for (int k = 0; k < 4; k++)
        xA[k] = __ldg((const int2*)(g_xh + (size_t)dstB[k] * FF + f));
    #pragma unroll
    for (int k = 0; k < 4; k++) dstB[k] = __ldg(&ep[4 + k].z);

    for (int c = 0; c < n; c += 4) {
        // gather x for chunk c+1
        int2 xB[4];
        #pragma unroll
        for (int k = 0; k < 4; k++)
            xB[k] = __ldg((const int2*)(g_xh + (size_t)dstB[k] * FF + f));
        // prefetch dst fields for chunk c+2 (also pulls record lines into L1)
        #pragma unroll
        for (int k = 0; k < 4; k++) dstB[k] = __ldg(&ep[c + 8 + k].z);
        // math on chunk c; weight int4 inline — line L1-hot from dst prefetch
        #pragma unroll
        for (int k = 0; k < 4; k++) {
            int4 rec = (c + k < n) ? __ldg(ep + c + k) : make_int4(0, 0, 0, 0);
            __half2 hw01 = *reinterpret_cast<__half2*>(&rec.x);
            __half2 hw23 = *reinterpret_cast<__half2*>(&rec.y);
            float2 w01 = __half22float2(hw01);
            float2 w23 = __half22float2(hw23);
            rs01 = fadd2(rs01, pack2(w01.x, w01.y));
            rs23 = fadd2(rs23, pack2(w23.x, w23.y));
            __half2 hx01 = *reinterpret_cast<__half2*>(&xA[k].x);
            __half2 hx23 = *reinterpret_cast<__half2*>(&xA[k].y);
            float2 x01 = __half22float2(hx01);
            float2 x23 = __half22float2(hx23);
            u64 xv01 = pack2(x01.x, x01.y);
            u64 xv23 = pack2(x23.x, x23.y);
            u64 p0 = dup2(w01.x), p1 = dup2(w01.y), p2 = dup2(w23.x), p3 = dup2(w23.y);
            acc[0][0] = ffma2(p0, xv01, acc[0][0]); acc[0][1] = ffma2(p0, xv23, acc[0][1]);
            acc[1][0] = ffma2(p1, xv01, acc[1][0]); acc[1][1] = ffma2(p1, xv23, acc[1][1]);
            acc[2][0] = ffma2(p2, xv01, acc[2][0]); acc[2][1] = ffma2(p2, xv23, acc[2][1]);
            acc[3][0] = ffma2(p3, xv01, acc[3][0]); acc[3][1] = ffma2(p3, xv23, acc[3][1]);
        }
        #pragma unroll
        for (int k = 0; k < 4; k++) xA[k] = xB[k];
    }

    float rs0, rs1, rs2, rs3;
    unpk2(rs01, rs0, rs1); unpk2(rs23, rs2, rs3);
    float inv[HH] = {1.0f / rs0, 1.0f / rs1, 1.0f / rs2, 1.0f / rs3};

    size_t base = (size_t)gw * FF + f;
    #pragma unroll
    for (int h = 0; h < HH; h++) {
        float4 wv = *(const float4*)(wp + h * FF + f);
        float a0, a1, a2, a3;
        unpk2(acc[h][0], a0, a1); unpk2(acc[h][1], a2, a3);
        __stcs((float4*)(out + (size_t)h * NN * FF + base),
            make_float4(a0 * wv.x * inv[h], a1 * wv.y * inv[h],
                        a2 * wv.z * inv[h], a3 * wv.w * inv[h]));
    }
}

// ---------------- launch -----------------------------------------------------
extern "C" void kernel_launch(void* const* d_in, const int* in_sizes, int n_in,
                              void* d_out, int out_size) {
    const float* x  = (const float*)d_in[0];
    const float* wp = (const float*)d_in[1];
    const float* ap = (const float*)d_in[2];
    const int*   ei = (const int*)d_in[3];
    float* out = (float*)d_out;

    const int TB = 256;
    k_prep<<<NODE_BLOCKS + HIST_BLOCKS, TB>>>(x, wp, ap, ei);
    k_scan<<<NBLK, 1024>>>();
    k_scatter<<<(NE / 2 + TB - 1) / TB, TB>>>(ei);
    k_agg<<<NODE_BLOCKS, TB>>>(wp, out);
}

// round 17
// speedup vs baseline: 1.0908x; 1.0748x over previous
#include <cuda_runtime.h>
#include <cuda_fp16.h>
#include <math.h>

#define NN 50000
#define NE 1600000
#define HH 4
#define FF 128
#define NBLK 49                 // ceil(50000/1024)
#define NODE_BLOCKS 6250        // NN*32/256
#define HIST_BLOCKS 3125        // (NE/2)/256 int4-loads
#define LOG2E 1.4426950408889634f

typedef unsigned long long u64;

// ---------------- scratch ----------------------------------------------------
__device__ int    g_is64;
__device__ int    g_deg[NN];          // zero at load; re-zeroed by k_scatter each call
__device__ int    g_off[NN + 1];
__device__ int    g_cursor[NN];
__device__ float4 g_ssrc[NN];         // pre-scaled by log2(e)
__device__ float4 g_sdst[NN];         // pre-scaled by log2(e)
__device__ int4   g_edges[NE + 16];   // {half2 w01, half2 w23, dst, 0}; pad stays zero

// ---------------- f32x2 helpers ----------------------------------------------
__device__ __forceinline__ u64 pack2(float a, float b) {
    u64 r; asm("mov.b64 %0,{%1,%2};" : "=l"(r) : "f"(a), "f"(b)); return r;
}
__device__ __forceinline__ u64 dup2(float a) { return pack2(a, a); }
__device__ __forceinline__ void unpk2(u64 v, float& a, float& b) {
    asm("mov.b64 {%0,%1},%2;" : "=f"(a), "=f"(b) : "l"(v));
}
__device__ __forceinline__ u64 ffma2(u64 a, u64 b, u64 c) {
    u64 d; asm("fma.rn.f32x2 %0,%1,%2,%3;" : "=l"(d) : "l"(a), "l"(b), "l"(c)); return d;
}
__device__ __forceinline__ u64 fadd2(u64 a, u64 b) {
    u64 d; asm("add.rn.f32x2 %0,%1,%2;" : "=l"(d) : "l"(a), "l"(b)); return d;
}

// ---------------- 1) fused prep (scores + detect) & hist ---------------------
__global__ void __launch_bounds__(256) k_prep(const float* __restrict__ x,
                                              const float* __restrict__ wp,
                                              const float* __restrict__ ap,
                                              const int* __restrict__ ei) {
    int b = blockIdx.x;
    if (b >= NODE_BLOCKS) {
        // histogram: coalesced int4 over the src array
        int t = (b - NODE_BLOCKS) * 256 + threadIdx.x;   // int4 index < NE/2
        int4 v = ((const int4*)ei)[t];
        __shared__ int any32;
        if (threadIdx.x == 0) any32 = 0;
        __syncthreads();
        if ((v.y | v.w) != 0) any32 = 1;
        __syncthreads();
        if (any32 == 0) {                 // int64 layout
            atomicAdd(&g_deg[v.x], 1);
            atomicAdd(&g_deg[v.z], 1);
        } else if (t < NE / 4) {          // int32 layout
            atomicAdd(&g_deg[v.x], 1);
            atomicAdd(&g_deg[v.y], 1);
            atomicAdd(&g_deg[v.z], 1);
            atomicAdd(&g_deg[v.w], 1);
        }
        return;
    }

    int tid = b * 256 + threadIdx.x;
    if (tid == 0) g_off[NN] = NE;
    if (b == 0) {
        __shared__ int bad;
        if (threadIdx.x == 0) bad = 0;
        __syncthreads();
        for (int k = threadIdx.x; k < 4096; k += 256)
            if (ei[2 * k + 1] != 0) bad = 1;
        __syncthreads();
        if (threadIdx.x == 0) g_is64 = (bad == 0) ? 1 : 0;
    }

    int gw   = tid >> 5;
    int lane = threadIdx.x & 31;
    int f = lane * 4;
    float4 xv = *(const float4*)(x + (size_t)gw * FF + f);

    float ss[HH], sd[HH];
    #pragma unroll
    for (int h = 0; h < HH; h++) {
        float4 wv = *(const float4*)(wp + h * FF + f);
        float4 as = *(const float4*)(ap + h * 2 * FF + f);
        float4 ad = *(const float4*)(ap + h * 2 * FF + FF + f);
        float4 hw = make_float4(xv.x * wv.x, xv.y * wv.y, xv.z * wv.z, xv.w * wv.w);
        float hs = hw.x * as.x + hw.y * as.y + hw.z * as.z + hw.w * as.w;
        float hd = hw.x * ad.x + hw.y * ad.y + hw.z * ad.z + hw.w * ad.w;
        #pragma unroll
        for (int o = 16; o; o >>= 1) {
            hs += __shfl_xor_sync(0xffffffffu, hs, o);
            hd += __shfl_xor_sync(0xffffffffu, hd, o);
        }
        ss[h] = hs * LOG2E; sd[h] = hd * LOG2E;   // pre-scale for ex2
    }
    if (lane == 0) {
        g_ssrc[gw] = make_float4(ss[0], ss[1], ss[2], ss[3]);
        g_sdst[gw] = make_float4(sd[0], sd[1], sd[2], sd[3]);
    }
}

// ---------------- 2) one-shot scan -------------------------------------------
__global__ void k_scan() {
    __shared__ int wsum[32];
    __shared__ int redsum[32];
    int b = blockIdx.x, t = threadIdx.x, lane = t & 31, wid = t >> 5;

    int pre = b * 1024;
    int acc = 0;
    for (int i = t; i < pre; i += 1024) acc += g_deg[i];
    #pragma unroll
    for (int o = 16; o; o >>= 1) acc += __shfl_xor_sync(0xffffffffu, acc, o);
    if (lane == 0) redsum[wid] = acc;
    __syncthreads();
    int bofs;
    {
        int v = redsum[lane];
        #pragma unroll
        for (int o = 16; o; o >>= 1) v += __shfl_xor_sync(0xffffffffu, v, o);
        bofs = __shfl_sync(0xffffffffu, v, 0);
    }

    int i = pre + t;
    int v = (i < NN) ? g_deg[i] : 0;
    int inc = v;
    #pragma unroll
    for (int o = 1; o < 32; o <<= 1) {
        int u = __shfl_up_sync(0xffffffffu, inc, o);
        if (lane >= o) inc += u;
    }
    if (lane == 31) wsum[wid] = inc;
    __syncthreads();
    if (wid == 0) {
        int s = wsum[lane];
        #pragma unroll
        for (int o = 1; o < 32; o <<= 1) {
            int u = __shfl_up_sync(0xffffffffu, s, o);
            if (lane >= o) s += u;
        }
        wsum[lane] = s;
    }
    __syncthreads();
    int excl = bofs + (wid ? wsum[wid - 1] : 0) + inc - v;
    if (i < NN) { g_off[i] = excl; g_cursor[i] = excl; }
}

// ---------------- 3) scatter: single 16B record store ------------------------
__device__ __forceinline__ float edge_w(float s2) {
    // scores pre-scaled by log2e: w = 2^min(-s2, -0.2*s2)
    float e = fminf(-s2, -0.2f * s2);
    float r; asm("ex2.approx.f32 %0,%1;" : "=f"(r) : "f"(e));
    return r;
}
__global__ void __launch_bounds__(256) k_scatter(const int* __restrict__ ei) {
    int i = blockIdx.x * blockDim.x + threadIdx.x;
    if (i < NN) g_deg[i] = 0;              // restore invariant for next call
    if (i >= NE / 2) return;               // 2 edges per thread
    int s0, s1, d0, d1;
    if (g_is64) {
        int4 sv = ((const int4*)ei)[i];
        int4 dv = ((const int4*)ei)[NE / 2 + i];
        s0 = sv.x; s1 = sv.z; d0 = dv.x; d1 = dv.z;
    } else {
        int2 sv = ((const int2*)ei)[i];
        int2 dv = ((const int2*)ei)[NE / 2 + i];
        s0 = sv.x; s1 = sv.y; d0 = dv.x; d1 = dv.y;
    }
    float4 a0 = g_ssrc[s0], b0 = g_sdst[d0];
    float4 a1 = g_ssrc[s1], b1 = g_sdst[d1];

    __half2 w001 = __floats2half2_rn(edge_w(a0.x + b0.x), edge_w(a0.y + b0.y));
    __half2 w023 = __floats2half2_rn(edge_w(a0.z + b0.z), edge_w(a0.w + b0.w));
    __half2 w101 = __floats2half2_rn(edge_w(a1.x + b1.x), edge_w(a1.y + b1.y));
    __half2 w123 = __floats2half2_rn(edge_w(a1.z + b1.z), edge_w(a1.w + b1.w));

    int p0 = atomicAdd(&g_cursor[s0], 1);
    int p1 = atomicAdd(&g_cursor[s1], 1);

    int4 r0, r1;
    r0.x = *reinterpret_cast<int*>(&w001); r0.y = *reinterpret_cast<int*>(&w023);
    r0.z = d0; r0.w = 0;
    r1.x = *reinterpret_cast<int*>(&w101); r1.y = *reinterpret_cast<int*>(&w123);
    r1.z = d1; r1.w = 0;
    g_edges[p0] = r0;
    g_edges[p1] = r1;
}

// ---------------- 4) aggregation: chunk-3 fp32-x double-buffered pipeline ----
__global__ void __launch_bounds__(256, 4) k_agg(const float* __restrict__ x,
                                                const float* __restrict__ wp,
                                                float* __restrict__ out) {
    int gw   = (blockIdx.x * blockDim.x + threadIdx.x) >> 5;
    int lane = threadIdx.x & 31;
    if (gw >= NN) return;
    int beg = g_off[gw];
    int n   = g_off[gw + 1] - beg;
    int f = lane * 4;
    const int4* ep = g_edges + beg;

    u64 acc[HH][2];
    #pragma unroll
    for (int h = 0; h < HH; h++) { acc[h][0] = 0ull; acc[h][1] = 0ull; }
    u64 rs01 = 0ull, rs23 = 0ull;

    // prologue: dsts of chunk0 -> gather xA (fp32, 16B); then dsts of chunk1
    int dstB[3];
    ulonglong2 xA[3];
    #pragma unroll
    for (int k = 0; k < 3; k++) dstB[k] = __ldg(&ep[k].z);          // padded: safe
    #pragma unroll
    for (int k = 0; k < 3; k++)
        xA[k] = __ldg((const ulonglong2*)(x + (size_t)dstB[k] * FF + f));
    #pragma unroll
    for (int k = 0; k < 3; k++) dstB[k] = __ldg(&ep[3 + k].z);

    for (int c = 0; c < n; c += 3) {
        // gather x for chunk c+1
        ulonglong2 xB[3];
        #pragma unroll
        for (int k = 0; k < 3; k++)
            xB[k] = __ldg((const ulonglong2*)(x + (size_t)dstB[k] * FF + f));
        // prefetch dsts for chunk c+2 (also warms record lines in L1)
        #pragma unroll
        for (int k = 0; k < 3; k++) dstB[k] = __ldg(&ep[c + 6 + k].z);
        // math on chunk c; weight int4 inline (L1-hot), predicated past n
        #pragma unroll
        for (int k = 0; k < 3; k++) {
            int4 rec = (c + k < n) ? __ldg(ep + c + k) : make_int4(0, 0, 0, 0);
            __half2 hw01 = *reinterpret_cast<__half2*>(&rec.x);
            __half2 hw23 = *reinterpret_cast<__half2*>(&rec.y);
            float2 w01 = __half22float2(hw01);
            float2 w23 = __half22float2(hw23);
            rs01 = fadd2(rs01, pack2(w01.x, w01.y));
            rs23 = fadd2(rs23, pack2(w23.x, w23.y));
            u64 xv01 = xA[k].x;               // fp32x2 direct from LDG.128
            u64 xv23 = xA[k].y;
            u64 p0 = dup2(w01.x), p1 = dup2(w01.y), p2 = dup2(w23.x), p3 = dup2(w23.y);
            acc[0][0] = ffma2(p0, xv01, acc[0][0]); acc[0][1] = ffma2(p0, xv23, acc[0][1]);
            acc[1][0] = ffma2(p1, xv01, acc[1][0]); acc[1][1] = ffma2(p1, xv23, acc[1][1]);
            acc[2][0] = ffma2(p2, xv01, acc[2][0]); acc[2][1] = ffma2(p2, xv23, acc[2][1]);
            acc[3][0] = ffma2(p3, xv01, acc[3][0]); acc[3][1] = ffma2(p3, xv23, acc[3][1]);
        }
        #pragma unroll
        for (int k = 0; k < 3; k++) xA[k] = xB[k];
    }

    float rs0, rs1, rs2, rs3;
    unpk2(rs01, rs0, rs1); unpk2(rs23, rs2, rs3);
    float inv[HH] = {1.0f / rs0, 1.0f / rs1, 1.0f / rs2, 1.0f / rs3};

    size_t base = (size_t)gw * FF + f;
    #pragma unroll
    for (int h = 0; h < HH; h++) {
        float4 wv = *(const float4*)(wp + h * FF + f);
        float a0, a1, a2, a3;
        unpk2(acc[h][0], a0, a1); unpk2(acc[h][1], a2, a3);
        __stcs((float4*)(out + (size_t)h * NN * FF + base),
            make_float4(a0 * wv.x * inv[h], a1 * wv.y * inv[h],
                        a2 * wv.z * inv[h], a3 * wv.w * inv[h]));
    }
}

// ---------------- launch -----------------------------------------------------
extern "C" void kernel_launch(void* const* d_in, const int* in_sizes, int n_in,
                              void* d_out, int out_size) {
    const float* x  = (const float*)d_in[0];
    const float* wp = (const float*)d_in[1];
    const float* ap = (const float*)d_in[2];
    const int*   ei = (const int*)d_in[3];
    float* out = (float*)d_out;

    const int TB = 256;
    k_prep<<<NODE_BLOCKS + HIST_BLOCKS, TB>>>(x, wp, ap, ei);
    k_scan<<<NBLK, 1024>>>();
    k_scatter<<<(NE / 2 + TB - 1) / TB, TB>>>(ei);
    k_agg<<<NODE_BLOCKS, TB>>>(x, wp, out);
}